// round 11
// baseline (speedup 1.0000x reference)
#include <cuda_runtime.h>
#include <cuda_fp16.h>
#include <cstdint>

// FusionAVWGCN: out = x@W0(n) + softmax(relu(E E^T))@x @ W1(n) + bias(n)
// B=8, N=8192, Cin=Cout=32, D=16, CHEB_K=2 (supports = [I, A])
// Fully tensor-core propagation; epilogue split into write-bound weight-gen
// GEMM (g_W) + lean streaming apply kernel.

#define NN 8192
#define BB 8
#define CI 32
#define DD 16

// ---------------- global scratch ----------------
static __device__ __half g_xh[NN * 256];           // [m][bc] fp16
static __device__ __half g_eh[DD * NN];            // [d][m] fp16 hi
static __device__ __half g_el[DD * NN];            // [d][m] fp16 lo
static __device__ float g_num[2][BB * NN * CI];    // split-K partial numerators
static __device__ float g_den2[2][NN];             // split-K partial denominators
static __device__ float g_M[2][NN];                // split-K row-max used
static __device__ float g_W[NN * 2 * CI * CI];     // [n][k][i][o] per-node weights

// ---------------- PTX helpers ----------------
__device__ __forceinline__ uint32_t smem_u32(const void* p) {
    uint32_t a;
    asm("{ .reg .u64 t; cvta.to.shared.u64 t, %1; cvt.u32.u64 %0, t; }" : "=r"(a) : "l"(p));
    return a;
}
__device__ __forceinline__ void cp16(void* dst, const void* src) {
    unsigned s = smem_u32(dst);
    asm volatile("cp.async.cg.shared.global [%0], [%1], 16;" :: "r"(s), "l"(src));
}
__device__ __forceinline__ void cp_commit() { asm volatile("cp.async.commit_group;"); }
template <int W> __device__ __forceinline__ void cp_wait() {
    asm volatile("cp.async.wait_group %0;" :: "n"(W));
}
__device__ __forceinline__ unsigned long long pack2(float a) {
    unsigned long long r; asm("mov.b64 %0, {%1, %1};" : "=l"(r) : "f"(a)); return r;
}
__device__ __forceinline__ void fma2(unsigned long long& d, unsigned long long a,
                                     unsigned long long b) {
    asm("fma.rn.f32x2 %0, %1, %2, %0;" : "+l"(d) : "l"(a), "l"(b));
}
__device__ __forceinline__ void unpack2(unsigned long long v, float& lo, float& hi) {
    asm("mov.b64 {%0, %1}, %2;" : "=f"(lo), "=f"(hi) : "l"(v));
}
__device__ __forceinline__ void ldsm4t(uint32_t* r, uint32_t addr) {
    asm volatile("ldmatrix.sync.aligned.m8n8.x4.trans.shared.b16 {%0,%1,%2,%3}, [%4];"
                 : "=r"(r[0]), "=r"(r[1]), "=r"(r[2]), "=r"(r[3]) : "r"(addr));
}
__device__ __forceinline__ void mma16816h(float* d, const uint32_t* a, const uint32_t* b) {
    asm volatile("mma.sync.aligned.m16n8k16.row.col.f32.f16.f16.f32 "
                 "{%0,%1,%2,%3}, {%4,%5,%6,%7}, {%8,%9}, {%0,%1,%2,%3};"
                 : "+f"(d[0]), "+f"(d[1]), "+f"(d[2]), "+f"(d[3])
                 : "r"(a[0]), "r"(a[1]), "r"(a[2]), "r"(a[3]), "r"(b[0]), "r"(b[1]));
}
__device__ __forceinline__ uint32_t hpack(float a, float b) {
    __half2 t = __floats2half2_rn(a, b);             // a -> low halfword
    return *(uint32_t*)&t;
}

// ---------------- smem layout (bytes) for prop ----------------
#define XBUF   32768                 // one x buffer: 64 rows x 512B (fp16)
#define OFF_E  65536                 // [2 buf][2 split][16 rows x 128B] = 8192
#define SMEM_PROP 73728

// ================= kernel 0: x -> fp16 [m][bc]; E -> fp16 hi/lo [d][m] =========
__global__ void __launch_bounds__(256) splitx_kernel(const float* __restrict__ x,
                                                     const float* __restrict__ E) {
    if (blockIdx.x < 4096) {
        const int id = blockIdx.x * 256 + threadIdx.x;
        const int e0 = id * 2;
        const int b = e0 >> 18;
        const int rem = e0 & 262143;
        const int m = rem >> 5, c = rem & 31;
        const float2 v = *(const float2*)(x + e0);
        *(uint32_t*)(g_xh + m * 256 + b * 32 + c) = hpack(v.x, v.y);
    } else {
        const int bl = blockIdx.x - 4096;            // 64 blocks x 128 rows
        const int m = bl * 128 + (threadIdx.x >> 1);
        const int d0 = (threadIdx.x & 1) * 8;
#pragma unroll
        for (int j = 0; j < 8; j++) {
            float v = E[m * DD + d0 + j];
            __half h = __float2half_rn(v);
            g_eh[(d0 + j) * NN + m] = h;
            g_el[(d0 + j) * NN + m] = __float2half_rn(v - __half2float(h));
        }
    }
}

// ================= kernel 1: all-tensor-core propagation =================
__global__ void __launch_bounds__(256, 1)
prop_kernel(const float* __restrict__ E) {
    extern __shared__ __align__(1024) char smem[];
    const uint32_t sb = smem_u32(smem);
    const int tid = threadIdx.x, lane = tid & 31, w = tid >> 5;
    const int half = blockIdx.x & 1, tile = blockIdx.x >> 1;
    const int mstart = half * 4096;

    const int q = lane >> 2, c = lane & 3;
    const int g = lane >> 3, rr = lane & 7;
    const int nr0 = tile * 128 + 16 * w + q;         // global n rows of this lane
    const int nr1 = nr0 + 8;

    // ---- loop-invariant A fragment: E_n split hi/lo ----
    uint32_t ahi[4], alo[4];
    {
        float v[8];
        v[0] = E[nr0 * DD + 2 * c];     v[1] = E[nr0 * DD + 2 * c + 1];
        v[2] = E[nr1 * DD + 2 * c];     v[3] = E[nr1 * DD + 2 * c + 1];
        v[4] = E[nr0 * DD + 8 + 2 * c]; v[5] = E[nr0 * DD + 8 + 2 * c + 1];
        v[6] = E[nr1 * DD + 8 + 2 * c]; v[7] = E[nr1 * DD + 8 + 2 * c + 1];
#pragma unroll
        for (int k = 0; k < 4; k++) {
            float a = v[2 * k], b = v[2 * k + 1];
            __half ha = __float2half_rn(a), hb = __float2half_rn(b);
            ahi[k] = hpack(__half2float(ha), __half2float(hb));
            alo[k] = hpack(a - __half2float(ha), b - __half2float(hb));
        }
    }

    const uint32_t b_rowb = (uint32_t)((g & 1) * 8 + rr);
    const uint32_t b_col = (uint32_t)(g >> 1);
    const uint32_t b_xor = (uint32_t)rr;
    const uint32_t e_row = b_rowb;

    float acc[32][4];
#pragma unroll
    for (int j = 0; j < 32; j++)
#pragma unroll
        for (int p = 0; p < 4; p++) acc[j][p] = 0.0f;

    float M0 = 0.0f, M1 = 0.0f, den0 = 0.0f, den1 = 0.0f;

    auto preload = [&](int ch) {
        const int buf = ch & 1;
        const int m0 = mstart + ch * 64;
        char* xb = smem + buf * XBUF;
#pragma unroll
        for (int j = 0; j < 8; j++) {
            int id = tid + j * 256;
            int row = id >> 5, s = id & 31;
            cp16(xb + row * 512 + ((s ^ (row & 7)) << 4),
                 g_xh + (m0 + row) * 256 + s * 8);
        }
        {
            int split = tid >> 7, row = (tid >> 3) & 15, seg = tid & 7;
            const __half* src = (split ? g_el : g_eh) + row * NN + m0 + seg * 8;
            cp16(smem + OFF_E + buf * 4096 + split * 2048 + row * 128 +
                     ((seg ^ (row & 7)) << 4),
                 src);
        }
        cp_commit();
    };

    preload(0);

#pragma unroll 1
    for (int i = 0; i < 64; i++) {
        const int buf = i & 1;
        cp_wait<0>();
        __syncthreads();
        if (i < 63) preload(i + 1);

        // ---- logits via MMA ----
        float D[8][4];
#pragma unroll
        for (int t = 0; t < 8; t++)
#pragma unroll
            for (int p = 0; p < 4; p++) D[t][p] = 0.0f;
        {
            const uint32_t Eb = sb + OFF_E + buf * 4096;
#pragma unroll
            for (int tp = 0; tp < 4; tp++) {
                const uint32_t cs = 2 * tp + b_col;
                const uint32_t off = e_row * 128 + (((cs ^ (e_row & 7)) & 7) << 4);
                uint32_t bh[4], bl[4];
                ldsm4t(bh, Eb + off);
                ldsm4t(bl, Eb + 2048 + off);
                mma16816h(D[2 * tp],     ahi, bh);
                mma16816h(D[2 * tp + 1], ahi, bh + 2);
                mma16816h(D[2 * tp],     ahi, bl);
                mma16816h(D[2 * tp + 1], ahi, bl + 2);
                mma16816h(D[2 * tp],     alo, bh);
                mma16816h(D[2 * tp + 1], alo, bh + 2);
            }
        }

        // ---- relu + chunk row max ----
        float cm0 = 0.0f, cm1 = 0.0f;
#pragma unroll
        for (int t = 0; t < 8; t++) {
            D[t][0] = fmaxf(D[t][0], 0.0f); D[t][1] = fmaxf(D[t][1], 0.0f);
            D[t][2] = fmaxf(D[t][2], 0.0f); D[t][3] = fmaxf(D[t][3], 0.0f);
            cm0 = fmaxf(cm0, fmaxf(D[t][0], D[t][1]));
            cm1 = fmaxf(cm1, fmaxf(D[t][2], D[t][3]));
        }
        cm0 = fmaxf(cm0, __shfl_xor_sync(0xffffffffu, cm0, 1));
        cm0 = fmaxf(cm0, __shfl_xor_sync(0xffffffffu, cm0, 2));
        cm1 = fmaxf(cm1, __shfl_xor_sync(0xffffffffu, cm1, 1));
        cm1 = fmaxf(cm1, __shfl_xor_sync(0xffffffffu, cm1, 2));

        if (cm0 > M0) {
            float s = __expf(M0 - cm0);
            den0 *= s;
#pragma unroll
            for (int jt = 0; jt < 32; jt++) { acc[jt][0] *= s; acc[jt][1] *= s; }
            M0 = cm0;
        }
        if (cm1 > M1) {
            float s = __expf(M1 - cm1);
            den1 *= s;
#pragma unroll
            for (int jt = 0; jt < 32; jt++) { acc[jt][2] *= s; acc[jt][3] *= s; }
            M1 = cm1;
        }

        // ---- p' = exp(l - M) into A fragments ----
        uint32_t ap[4][4];
#pragma unroll
        for (int kk = 0; kk < 4; kk++) {
            const int t0 = 2 * kk, t1 = t0 + 1;
            ap[kk][0] = hpack(__expf(D[t0][0] - M0), __expf(D[t0][1] - M0));
            ap[kk][1] = hpack(__expf(D[t0][2] - M1), __expf(D[t0][3] - M1));
            ap[kk][2] = hpack(__expf(D[t1][0] - M0), __expf(D[t1][1] - M0));
            ap[kk][3] = hpack(__expf(D[t1][2] - M1), __expf(D[t1][3] - M1));
            float2 u0 = __half22float2(*(__half2*)&ap[kk][0]);
            float2 u2 = __half22float2(*(__half2*)&ap[kk][2]);
            den0 += u0.x + u0.y + u2.x + u2.y;
            float2 u1 = __half22float2(*(__half2*)&ap[kk][1]);
            float2 u3 = __half22float2(*(__half2*)&ap[kk][3]);
            den1 += u1.x + u1.y + u3.x + u3.y;
        }

        // ---- main MMA: acc += P' * X ----
        {
            const uint32_t Xb = sb + buf * XBUF;
#pragma unroll
            for (int kk = 0; kk < 4; kk++) {
                const uint32_t brow = (b_rowb + kk * 16) * 512;
#pragma unroll
                for (int j = 0; j < 16; j++) {
                    const uint32_t q2 = 2 * j + b_col;
                    const uint32_t boff = brow + (((q2 ^ b_xor) & 63) << 4);
                    uint32_t bh[4];
                    ldsm4t(bh, Xb + boff);
                    mma16816h(acc[2 * j],     ap[kk], bh);
                    mma16816h(acc[2 * j + 1], ap[kk], bh + 2);
                }
            }
        }
    }

    den0 += __shfl_xor_sync(0xffffffffu, den0, 1);
    den0 += __shfl_xor_sync(0xffffffffu, den0, 2);
    den1 += __shfl_xor_sync(0xffffffffu, den1, 1);
    den1 += __shfl_xor_sync(0xffffffffu, den1, 2);
    if (c == 0) {
        g_den2[half][nr0] = den0; g_den2[half][nr1] = den1;
        g_M[half][nr0] = M0;      g_M[half][nr1] = M1;
    }

    {
        const int rlo = 16 * w + (lane >> 2);
        const int cpair = (lane & 3) * 2;
        float* base = g_num[half];
#pragma unroll
        for (int jt = 0; jt < 32; jt++) {
            const int bc = jt * 8 + cpair;
            const int b = bc >> 5, cc = bc & 31;
            const int n = tile * 128 + rlo;
            *(float2*)(base + (b * NN + n) * CI + cc) = make_float2(acc[jt][0], acc[jt][1]);
            *(float2*)(base + (b * NN + n + 8) * CI + cc) = make_float2(acc[jt][2], acc[jt][3]);
        }
    }
}

// ================= kernel 2a: weight-gen GEMM  W[n,k,i,o] = E[n]·Wp =========
__global__ void __launch_bounds__(256, 1)
wgen_kernel(const float* __restrict__ E, const float* __restrict__ Wp) {
    extern __shared__ float sm[];
    float* sWp = sm;                                   // 32768 floats [d][k][i][o]
    unsigned long long* sEp = (unsigned long long*)(sm + 32768);  // [64][16] packed

    const int tid = threadIdx.x;
    const int n0 = blockIdx.x * 64;

#pragma unroll
    for (int k = 0; k < 32; k++) {
        int idx = (tid + (k << 8)) << 2;
        cp16(sWp + idx, Wp + idx);
    }
#pragma unroll
    for (int j = 0; j < 4; j++) {
        int id = tid + j * 256;
        int nl = id >> 4, d = id & 15;
        sEp[nl * 16 + d] = pack2(E[(n0 + nl) * DD + d]);
    }
    cp_commit();
    cp_wait<0>();
    __syncthreads();

#pragma unroll 1
    for (int jj = 0; jj < 4; jj++) {
        const int pidx = tid + jj * 256;               // [0,1024)
        const int k = pidx >> 9, i = (pidx >> 4) & 31, op = pidx & 15;
        unsigned long long wv[16];
        const float* src = sWp + k * 1024 + i * 32 + op * 2;
#pragma unroll
        for (int d = 0; d < 16; d++)
            wv[d] = *(const unsigned long long*)(src + (d << 11));
        float* dst = g_W + n0 * 2048 + k * 1024 + i * 32 + op * 2;
#pragma unroll 2
        for (int n = 0; n < 64; n++) {
            const unsigned long long* ep = sEp + (n << 4);
            unsigned long long a0 = 0ULL, a1 = 0ULL;
#pragma unroll
            for (int d = 0; d < 8; d++) {
                fma2(a0, ep[d], wv[d]);
                fma2(a1, ep[d + 8], wv[d + 8]);
            }
            float l0, h0, l1, h1;
            unpack2(a0, l0, h0); unpack2(a1, l1, h1);
            *(float2*)(dst + n * 2048) = make_float2(l0 + l1, h0 + h1);
        }
    }
}

// ================= kernel 2b: streaming apply =================
// out[b,n,o] = bias + sum_i x[b,n,i]*W0[n,i,o] + ynorm[b,n,i]*W1[n,i,o]
__global__ void __launch_bounds__(256)
apply_kernel(const float* __restrict__ x, const float* __restrict__ E,
             const float* __restrict__ bp, float* __restrict__ out) {
    extern __shared__ float smA[];
    float* sx = smA;              // 8192
    float* sy = sx + 8192;        // 8192
    float* sS0 = sy + 8192;       // 32
    float* sS1 = sS0 + 32;        // 32

    const int tid = threadIdx.x;
    const int n0 = blockIdx.x * 32;

    if (tid < 32) {
        const int n = n0 + tid;
        float m0 = g_M[0][n], m1 = g_M[1][n];
        float mx = fmaxf(m0, m1);
        float s0 = __expf(m0 - mx), s1 = __expf(m1 - mx);
        float invd = 1.0f / (g_den2[0][n] * s0 + g_den2[1][n] * s1);
        sS0[tid] = s0 * invd;
        sS1[tid] = s1 * invd;
    }
    __syncthreads();

#pragma unroll
    for (int k = 0; k < 8; k++) {
        int f = (tid + (k << 8)) << 2;
        int nl = f >> 8, b = (f >> 5) & 7, i0 = f & 31;
        const int gi = (b * NN + n0 + nl) * CI + i0;
        *(float4*)(sx + f) = *(const float4*)(x + gi);
        float s0 = sS0[nl], s1 = sS1[nl];
        float4 y0 = *(const float4*)(g_num[0] + gi);
        float4 y1 = *(const float4*)(g_num[1] + gi);
        *(float4*)(sy + f) = make_float4(y0.x * s0 + y1.x * s1, y0.y * s0 + y1.y * s1,
                                         y0.z * s0 + y1.z * s1, y0.w * s0 + y1.w * s1);
    }
    __syncthreads();

    const int lane = tid & 31;    // output channel o
    const int w = tid >> 5;

#pragma unroll 1
    for (int r = 0; r < 4; r++) {
        const int nl = (r << 3) + w;
        const int n = n0 + nl;

        float e[DD];
#pragma unroll
        for (int d = 0; d < DD; d += 4)
            *(float4*)(e + d) = *(const float4*)(E + n * DD + d);

        float bias = 0.0f;
#pragma unroll
        for (int d = 0; d < DD; d++) bias = fmaf(e[d], __ldg(bp + (d << 5) + lane), bias);

        float acc[BB];
#pragma unroll
        for (int b = 0; b < BB; b++) acc[b] = bias;

        const float* W0 = g_W + n * 2048 + lane;
        const float* W1 = W0 + 1024;
        const float* xrow = sx + nl * 256;
        const float* yrow = sy + nl * 256;

#pragma unroll 4
        for (int i = 0; i < 32; i++) {
            float w0 = __ldg(W0 + i * 32);
            float w1 = __ldg(W1 + i * 32);
#pragma unroll
            for (int b = 0; b < BB; b++)
                acc[b] = fmaf(xrow[(b << 5) + i], w0, fmaf(yrow[(b << 5) + i], w1, acc[b]));
        }

#pragma unroll
        for (int b = 0; b < BB; b++)
            out[(b * NN + n) * CI + lane] = acc[b];
    }
}

// ---------------- launch ----------------
extern "C" void kernel_launch(void* const* d_in, const int* in_sizes, int n_in,
                              void* d_out, int out_size) {
    const float *x = nullptr, *E = nullptr, *Wp = nullptr, *bp = nullptr;
    for (int i = 0; i < n_in; i++) {
        switch (in_sizes[i]) {
            case BB * NN * CI:     x  = (const float*)d_in[i]; break;
            case NN * DD:          E  = (const float*)d_in[i]; break;
            case DD * 2 * CI * CI: Wp = (const float*)d_in[i]; break;
            case DD * CI:          bp = (const float*)d_in[i]; break;
        }
    }
    const int smem_wgen = (32768 + 64 * 16 * 2) * (int)sizeof(float);   // 139264
    const int smem_apply = (8192 + 8192 + 64) * (int)sizeof(float);     // 65792
    cudaFuncSetAttribute(prop_kernel, cudaFuncAttributeMaxDynamicSharedMemorySize, SMEM_PROP);
    cudaFuncSetAttribute(wgen_kernel, cudaFuncAttributeMaxDynamicSharedMemorySize, smem_wgen);
    cudaFuncSetAttribute(apply_kernel, cudaFuncAttributeMaxDynamicSharedMemorySize, smem_apply);

    splitx_kernel<<<4096 + 64, 256>>>(x, E);
    wgen_kernel<<<NN / 64, 256, smem_wgen>>>(E, Wp);
    prop_kernel<<<128, 256, SMEM_PROP>>>(E);
    apply_kernel<<<NN / 32, 256, smem_apply>>>(x, E, bp, (float*)d_out);
}

// round 12
// speedup vs baseline: 1.2511x; 1.2511x over previous
#include <cuda_runtime.h>
#include <cuda_fp16.h>
#include <cstdint>

// FusionAVWGCN: out = x@W0(n) + softmax(relu(E E^T))@x @ W1(n) + bias(n)
// B=8, N=8192, Cin=Cout=32, D=16, CHEB_K=2 (supports = [I, A])
// Tensor-core propagation (fp16 mma.sync, flash-style online max);
// fused fp32 epilogue with loop-interchanged weight generation.

#define NN 8192
#define BB 8
#define CI 32
#define DD 16

// ---------------- global scratch ----------------
static __device__ __half g_xh[NN * 256];           // [m][bc] fp16
static __device__ __half g_eh[DD * NN];            // [d][m] fp16 hi
static __device__ __half g_el[DD * NN];            // [d][m] fp16 lo
static __device__ float g_num[2][BB * NN * CI];    // split-K partial numerators
static __device__ float g_den2[2][NN];             // split-K partial denominators
static __device__ float g_M[2][NN];                // split-K row-max used

// ---------------- PTX helpers ----------------
__device__ __forceinline__ uint32_t smem_u32(const void* p) {
    uint32_t a;
    asm("{ .reg .u64 t; cvta.to.shared.u64 t, %1; cvt.u32.u64 %0, t; }" : "=r"(a) : "l"(p));
    return a;
}
__device__ __forceinline__ void cp16(void* dst, const void* src) {
    unsigned s = smem_u32(dst);
    asm volatile("cp.async.cg.shared.global [%0], [%1], 16;" :: "r"(s), "l"(src));
}
__device__ __forceinline__ void cp_commit() { asm volatile("cp.async.commit_group;"); }
template <int W> __device__ __forceinline__ void cp_wait() {
    asm volatile("cp.async.wait_group %0;" :: "n"(W));
}
__device__ __forceinline__ unsigned long long pack2(float a) {
    unsigned long long r; asm("mov.b64 %0, {%1, %1};" : "=l"(r) : "f"(a)); return r;
}
__device__ __forceinline__ void fma2(unsigned long long& d, unsigned long long a,
                                     unsigned long long b) {
    asm("fma.rn.f32x2 %0, %1, %2, %0;" : "+l"(d) : "l"(a), "l"(b));
}
__device__ __forceinline__ void unpack2(unsigned long long v, float& lo, float& hi) {
    asm("mov.b64 {%0, %1}, %2;" : "=f"(lo), "=f"(hi) : "l"(v));
}
__device__ __forceinline__ void ldsm4t(uint32_t* r, uint32_t addr) {
    asm volatile("ldmatrix.sync.aligned.m8n8.x4.trans.shared.b16 {%0,%1,%2,%3}, [%4];"
                 : "=r"(r[0]), "=r"(r[1]), "=r"(r[2]), "=r"(r[3]) : "r"(addr));
}
__device__ __forceinline__ void mma16816h(float* d, const uint32_t* a, const uint32_t* b) {
    asm volatile("mma.sync.aligned.m16n8k16.row.col.f32.f16.f16.f32 "
                 "{%0,%1,%2,%3}, {%4,%5,%6,%7}, {%8,%9}, {%0,%1,%2,%3};"
                 : "+f"(d[0]), "+f"(d[1]), "+f"(d[2]), "+f"(d[3])
                 : "r"(a[0]), "r"(a[1]), "r"(a[2]), "r"(a[3]), "r"(b[0]), "r"(b[1]));
}
__device__ __forceinline__ uint32_t hpack(float a, float b) {
    __half2 t = __floats2half2_rn(a, b);             // a -> low halfword
    return *(uint32_t*)&t;
}

// ---------------- smem layout (bytes) for prop ----------------
#define XBUF   32768                 // one x buffer: 64 rows x 512B (fp16)
#define OFF_E  65536                 // [2 buf][2 split][16 rows x 128B] = 8192
#define SMEM_PROP 73728

// ================= kernel 0: x -> fp16 [m][bc]; E -> fp16 hi/lo [d][m] =========
__global__ void __launch_bounds__(256) splitx_kernel(const float* __restrict__ x,
                                                     const float* __restrict__ E) {
    if (blockIdx.x < 4096) {
        const int id = blockIdx.x * 256 + threadIdx.x;
        const int e0 = id * 2;
        const int b = e0 >> 18;
        const int rem = e0 & 262143;
        const int m = rem >> 5, c = rem & 31;
        const float2 v = *(const float2*)(x + e0);
        *(uint32_t*)(g_xh + m * 256 + b * 32 + c) = hpack(v.x, v.y);
    } else {
        const int bl = blockIdx.x - 4096;            // 64 blocks x 128 rows
        const int m = bl * 128 + (threadIdx.x >> 1);
        const int d0 = (threadIdx.x & 1) * 8;
#pragma unroll
        for (int j = 0; j < 8; j++) {
            float v = E[m * DD + d0 + j];
            __half h = __float2half_rn(v);
            g_eh[(d0 + j) * NN + m] = h;
            g_el[(d0 + j) * NN + m] = __float2half_rn(v - __half2float(h));
        }
    }
}

// ================= kernel 1: all-tensor-core propagation =================
__global__ void __launch_bounds__(256, 1)
prop_kernel(const float* __restrict__ E) {
    extern __shared__ __align__(1024) char smem[];
    const uint32_t sb = smem_u32(smem);
    const int tid = threadIdx.x, lane = tid & 31, w = tid >> 5;
    const int half = blockIdx.x & 1, tile = blockIdx.x >> 1;
    const int mstart = half * 4096;

    const int q = lane >> 2, c = lane & 3;
    const int g = lane >> 3, rr = lane & 7;
    const int nr0 = tile * 128 + 16 * w + q;         // global n rows of this lane
    const int nr1 = nr0 + 8;

    // ---- loop-invariant A fragment: E_n split hi/lo ----
    uint32_t ahi[4], alo[4];
    {
        float v[8];
        v[0] = E[nr0 * DD + 2 * c];     v[1] = E[nr0 * DD + 2 * c + 1];
        v[2] = E[nr1 * DD + 2 * c];     v[3] = E[nr1 * DD + 2 * c + 1];
        v[4] = E[nr0 * DD + 8 + 2 * c]; v[5] = E[nr0 * DD + 8 + 2 * c + 1];
        v[6] = E[nr1 * DD + 8 + 2 * c]; v[7] = E[nr1 * DD + 8 + 2 * c + 1];
#pragma unroll
        for (int k = 0; k < 4; k++) {
            float a = v[2 * k], b = v[2 * k + 1];
            __half ha = __float2half_rn(a), hb = __float2half_rn(b);
            ahi[k] = hpack(__half2float(ha), __half2float(hb));
            alo[k] = hpack(a - __half2float(ha), b - __half2float(hb));
        }
    }

    const uint32_t b_rowb = (uint32_t)((g & 1) * 8 + rr);
    const uint32_t b_col = (uint32_t)(g >> 1);
    const uint32_t b_xor = (uint32_t)rr;
    const uint32_t e_row = b_rowb;

    float acc[32][4];
#pragma unroll
    for (int j = 0; j < 32; j++)
#pragma unroll
        for (int p = 0; p < 4; p++) acc[j][p] = 0.0f;

    float M0 = 0.0f, M1 = 0.0f, den0 = 0.0f, den1 = 0.0f;

    auto preload = [&](int ch) {
        const int buf = ch & 1;
        const int m0 = mstart + ch * 64;
        char* xb = smem + buf * XBUF;
#pragma unroll
        for (int j = 0; j < 8; j++) {
            int id = tid + j * 256;
            int row = id >> 5, s = id & 31;
            cp16(xb + row * 512 + ((s ^ (row & 7)) << 4),
                 g_xh + (m0 + row) * 256 + s * 8);
        }
        {
            int split = tid >> 7, row = (tid >> 3) & 15, seg = tid & 7;
            const __half* src = (split ? g_el : g_eh) + row * NN + m0 + seg * 8;
            cp16(smem + OFF_E + buf * 4096 + split * 2048 + row * 128 +
                     ((seg ^ (row & 7)) << 4),
                 src);
        }
        cp_commit();
    };

    preload(0);

#pragma unroll 1
    for (int i = 0; i < 64; i++) {
        const int buf = i & 1;
        cp_wait<0>();
        __syncthreads();
        if (i < 63) preload(i + 1);

        // ---- logits via MMA ----
        float D[8][4];
#pragma unroll
        for (int t = 0; t < 8; t++)
#pragma unroll
            for (int p = 0; p < 4; p++) D[t][p] = 0.0f;
        {
            const uint32_t Eb = sb + OFF_E + buf * 4096;
#pragma unroll
            for (int tp = 0; tp < 4; tp++) {
                const uint32_t cs = 2 * tp + b_col;
                const uint32_t off = e_row * 128 + (((cs ^ (e_row & 7)) & 7) << 4);
                uint32_t bh[4], bl[4];
                ldsm4t(bh, Eb + off);
                ldsm4t(bl, Eb + 2048 + off);
                mma16816h(D[2 * tp],     ahi, bh);
                mma16816h(D[2 * tp + 1], ahi, bh + 2);
                mma16816h(D[2 * tp],     ahi, bl);
                mma16816h(D[2 * tp + 1], ahi, bl + 2);
                mma16816h(D[2 * tp],     alo, bh);
                mma16816h(D[2 * tp + 1], alo, bh + 2);
            }
        }

        // ---- relu + chunk row max ----
        float cm0 = 0.0f, cm1 = 0.0f;
#pragma unroll
        for (int t = 0; t < 8; t++) {
            D[t][0] = fmaxf(D[t][0], 0.0f); D[t][1] = fmaxf(D[t][1], 0.0f);
            D[t][2] = fmaxf(D[t][2], 0.0f); D[t][3] = fmaxf(D[t][3], 0.0f);
            cm0 = fmaxf(cm0, fmaxf(D[t][0], D[t][1]));
            cm1 = fmaxf(cm1, fmaxf(D[t][2], D[t][3]));
        }
        cm0 = fmaxf(cm0, __shfl_xor_sync(0xffffffffu, cm0, 1));
        cm0 = fmaxf(cm0, __shfl_xor_sync(0xffffffffu, cm0, 2));
        cm1 = fmaxf(cm1, __shfl_xor_sync(0xffffffffu, cm1, 1));
        cm1 = fmaxf(cm1, __shfl_xor_sync(0xffffffffu, cm1, 2));

        if (cm0 > M0) {
            float s = __expf(M0 - cm0);
            den0 *= s;
#pragma unroll
            for (int jt = 0; jt < 32; jt++) { acc[jt][0] *= s; acc[jt][1] *= s; }
            M0 = cm0;
        }
        if (cm1 > M1) {
            float s = __expf(M1 - cm1);
            den1 *= s;
#pragma unroll
            for (int jt = 0; jt < 32; jt++) { acc[jt][2] *= s; acc[jt][3] *= s; }
            M1 = cm1;
        }

        // ---- p' = exp(l - M) into A fragments ----
        uint32_t ap[4][4];
#pragma unroll
        for (int kk = 0; kk < 4; kk++) {
            const int t0 = 2 * kk, t1 = t0 + 1;
            ap[kk][0] = hpack(__expf(D[t0][0] - M0), __expf(D[t0][1] - M0));
            ap[kk][1] = hpack(__expf(D[t0][2] - M1), __expf(D[t0][3] - M1));
            ap[kk][2] = hpack(__expf(D[t1][0] - M0), __expf(D[t1][1] - M0));
            ap[kk][3] = hpack(__expf(D[t1][2] - M1), __expf(D[t1][3] - M1));
            float2 u0 = __half22float2(*(__half2*)&ap[kk][0]);
            float2 u2 = __half22float2(*(__half2*)&ap[kk][2]);
            den0 += u0.x + u0.y + u2.x + u2.y;
            float2 u1 = __half22float2(*(__half2*)&ap[kk][1]);
            float2 u3 = __half22float2(*(__half2*)&ap[kk][3]);
            den1 += u1.x + u1.y + u3.x + u3.y;
        }

        // ---- main MMA: acc += P' * X ----
        {
            const uint32_t Xb = sb + buf * XBUF;
#pragma unroll
            for (int kk = 0; kk < 4; kk++) {
                const uint32_t brow = (b_rowb + kk * 16) * 512;
#pragma unroll
                for (int j = 0; j < 16; j++) {
                    const uint32_t q2 = 2 * j + b_col;
                    const uint32_t boff = brow + (((q2 ^ b_xor) & 63) << 4);
                    uint32_t bh[4];
                    ldsm4t(bh, Xb + boff);
                    mma16816h(acc[2 * j],     ap[kk], bh);
                    mma16816h(acc[2 * j + 1], ap[kk], bh + 2);
                }
            }
        }
    }

    den0 += __shfl_xor_sync(0xffffffffu, den0, 1);
    den0 += __shfl_xor_sync(0xffffffffu, den0, 2);
    den1 += __shfl_xor_sync(0xffffffffu, den1, 1);
    den1 += __shfl_xor_sync(0xffffffffu, den1, 2);
    if (c == 0) {
        g_den2[half][nr0] = den0; g_den2[half][nr1] = den1;
        g_M[half][nr0] = M0;      g_M[half][nr1] = M1;
    }

    {
        const int rlo = 16 * w + (lane >> 2);
        const int cpair = (lane & 3) * 2;
        float* base = g_num[half];
#pragma unroll
        for (int jt = 0; jt < 32; jt++) {
            const int bc = jt * 8 + cpair;
            const int b = bc >> 5, cc = bc & 31;
            const int n = tile * 128 + rlo;
            *(float2*)(base + (b * NN + n) * CI + cc) = make_float2(acc[jt][0], acc[jt][1]);
            *(float2*)(base + (b * NN + n + 8) * CI + cc) = make_float2(acc[jt][2], acc[jt][3]);
        }
    }
}

// ================= kernel 2: fused epilogue (loop-interchanged wgen) ==========
// out[b,n,o] = bias[n,o] + sum_i x[b,n,i]*W0[n,i,o] + ynorm[b,n,i]*W1[n,i,o]
// Wk[n,i,o] = sum_d E[n,d]*Wp[d,k,i,o]; each thread covers 4 node rows so every
// Wp operand is loaded from smem ONCE per (i,d) and reused 4x.
__global__ void __launch_bounds__(256, 1)
epi_kernel(const float* __restrict__ x, const float* __restrict__ E,
           const float* __restrict__ Wp, const float* __restrict__ bp,
           float* __restrict__ out) {
    extern __shared__ float sm[];
    float* sW = sm;               // 32768: layout ((d*32+i)*32+o)*2 + k
    float* sx = sm + 32768;       // [nl][b][i]
    float* sy = sx + 8192;        // normalized y
    float* sS0 = sy + 8192;       // 32: s0*invd
    float* sS1 = sS0 + 32;        // 32: s1*invd

    const int tid = threadIdx.x;
    const int n0 = blockIdx.x * 32;

    if (tid < 32) {
        const int n = n0 + tid;
        float m0 = g_M[0][n], m1 = g_M[1][n];
        float mx = fmaxf(m0, m1);
        float s0 = __expf(m0 - mx), s1 = __expf(m1 - mx);
        float invd = 1.0f / (g_den2[0][n] * s0 + g_den2[1][n] * s1);
        sS0[tid] = s0 * invd;
        sS1[tid] = s1 * invd;
    }
    __syncthreads();

    // stage Wp in pair layout
#pragma unroll
    for (int jj = 0; jj < 32; jj++) {
        int g4 = tid + jj * 256;
        int gg = g4 * 4;
        float4 v = *(const float4*)(Wp + gg);
        int o0 = gg & 31, ii = (gg >> 5) & 31, k = (gg >> 10) & 1, d = gg >> 11;
        float* dst = sW + ((d * 32 + ii) * 32 + o0) * 2 + k;
        dst[0] = v.x; dst[2] = v.y; dst[4] = v.z; dst[6] = v.w;
    }
    // stage x (cp.async) and normalized y
#pragma unroll
    for (int k = 0; k < 8; k++) {
        int f = (tid + (k << 8)) << 2;
        int nl = f >> 8, b = (f >> 5) & 7, i0 = f & 31;
        const int gi = (b * NN + n0 + nl) * CI + i0;
        cp16(sx + f, x + gi);
        float s0 = sS0[nl], s1 = sS1[nl];
        float4 y0 = *(const float4*)(g_num[0] + gi);
        float4 y1 = *(const float4*)(g_num[1] + gi);
        *(float4*)(sy + f) = make_float4(y0.x * s0 + y1.x * s1, y0.y * s0 + y1.y * s1,
                                         y0.z * s0 + y1.z * s1, y0.w * s0 + y1.w * s1);
    }
    cp_commit();
    cp_wait<0>();
    __syncthreads();

    const int lane = tid & 31;    // output channel o
    const int w = tid >> 5;

    // per-thread: 4 node rows nl = r*8 + w
    float e[4][DD];
    float acc[4][BB];
#pragma unroll
    for (int r = 0; r < 4; r++) {
        const int n = n0 + r * 8 + w;
#pragma unroll
        for (int d = 0; d < DD; d += 4)
            *(float4*)(&e[r][d]) = *(const float4*)(E + n * DD + d);
        float bias = 0.0f;
#pragma unroll
        for (int d = 0; d < DD; d++) bias = fmaf(e[r][d], __ldg(bp + (d << 5) + lane), bias);
#pragma unroll
        for (int b = 0; b < BB; b++) acc[r][b] = bias;
    }

#pragma unroll 2
    for (int i = 0; i < 32; i++) {
        unsigned long long w01[4] = {0ULL, 0ULL, 0ULL, 0ULL};
        const float* wp = sW + ((i * 32 + lane) << 1);
#pragma unroll
        for (int d = 0; d < DD; d++) {
            const unsigned long long wv = *(const unsigned long long*)(wp + (d << 11));
            fma2(w01[0], pack2(e[0][d]), wv);
            fma2(w01[1], pack2(e[1][d]), wv);
            fma2(w01[2], pack2(e[2][d]), wv);
            fma2(w01[3], pack2(e[3][d]), wv);
        }
#pragma unroll
        for (int r = 0; r < 4; r++) {
            float w0, w1;
            unpack2(w01[r], w0, w1);
            const float* xr = sx + ((r * 8 + w) << 8);
            const float* yr = sy + ((r * 8 + w) << 8);
#pragma unroll
            for (int b = 0; b < BB; b++)
                acc[r][b] = fmaf(xr[(b << 5) + i], w0, fmaf(yr[(b << 5) + i], w1, acc[r][b]));
        }
    }

#pragma unroll
    for (int r = 0; r < 4; r++) {
        const int n = n0 + r * 8 + w;
#pragma unroll
        for (int b = 0; b < BB; b++)
            out[(b * NN + n) * CI + lane] = acc[r][b];
    }
}

// ---------------- launch ----------------
extern "C" void kernel_launch(void* const* d_in, const int* in_sizes, int n_in,
                              void* d_out, int out_size) {
    const float *x = nullptr, *E = nullptr, *Wp = nullptr, *bp = nullptr;
    for (int i = 0; i < n_in; i++) {
        switch (in_sizes[i]) {
            case BB * NN * CI:     x  = (const float*)d_in[i]; break;
            case NN * DD:          E  = (const float*)d_in[i]; break;
            case DD * 2 * CI * CI: Wp = (const float*)d_in[i]; break;
            case DD * CI:          bp = (const float*)d_in[i]; break;
        }
    }
    const int smem_epi = (32768 + 8192 + 8192 + 64) * (int)sizeof(float);  // 196864
    cudaFuncSetAttribute(prop_kernel, cudaFuncAttributeMaxDynamicSharedMemorySize, SMEM_PROP);
    cudaFuncSetAttribute(epi_kernel, cudaFuncAttributeMaxDynamicSharedMemorySize, smem_epi);

    splitx_kernel<<<4096 + 64, 256>>>(x, E);
    prop_kernel<<<128, 256, SMEM_PROP>>>(E);
    epi_kernel<<<NN / 32, 256, smem_epi>>>(x, E, Wp, bp, (float*)d_out);
}